// round 1
// baseline (speedup 1.0000x reference)
#include <cuda_runtime.h>
#include <math.h>

#define DIMS    256
#define VOCAB   4096
#define HEADS   2
#define NB      2
#define SEQ     1024
#define DH      128            // DIMS / HEADS
#define TOKENS  (NB * SEQ)     // 2048
#define NLAYERS 6

// ---------------- scratch (static device memory; no allocs) ----------------
__device__ float g_x[TOKENS * DIMS];                    // activations [b,s,d]
__device__ float g_q[NB * HEADS * SEQ * DH];            // [b,h,s,d]
__device__ float g_kt[NB * HEADS * DH * SEQ];           // [b,h,d,s]  (K transposed)
__device__ float g_v[NB * HEADS * SEQ * DH];            // [b,h,s,d]
__device__ float g_s[(size_t)NB * HEADS * SEQ * SEQ];   // scores/probs [b,h,q,k]
__device__ float g_attn[TOKENS * DIMS];                 // head-concat attention out
__device__ float g_a[TOKENS * DIMS];                    // after Wo
__device__ float g_h[TOKENS * 2 * DIMS];                // MLP hidden

// ---------------- encoder: x[b,s,o] = sum_j W_enc[o, X[b,s], j] * pos[s,j] + b_enc[o]
__global__ __launch_bounds__(256) void encode_kernel(
    const int* __restrict__ X, const float* __restrict__ W_enc,
    const float* __restrict__ b_enc, float* __restrict__ xout)
{
    const int t = blockIdx.x;            // token 0..2047
    const int s = t & (SEQ - 1);
    const int tid = threadIdx.x;

    __shared__ float pos[DIMS];
    {
        const int i = tid;
        const float p = (float)NB - (float)s;    // positions = B - arange(S)
        const int fi = (i < DH) ? i : i - DH;    // half = 128
        const float invf = 1.0f / powf(10000.0f, (float)fi * (1.0f / 128.0f));
        const float ang = p * invf;
        pos[i] = (i < DH) ? sinf(ang) : cosf(ang);
    }
    __syncthreads();

    const int tok = X[t];
    const int warp = tid >> 5, lane = tid & 31;

    #pragma unroll
    for (int o = warp; o < DIMS; o += 8) {
        const float* wrow = W_enc + ((size_t)o * VOCAB + tok) * DIMS;
        const float4* w4 = reinterpret_cast<const float4*>(wrow);
        const float4* p4 = reinterpret_cast<const float4*>(pos);
        float4 wa = w4[lane * 2 + 0], wb = w4[lane * 2 + 1];
        float4 pa = p4[lane * 2 + 0], pb = p4[lane * 2 + 1];
        float acc = wa.x * pa.x + wa.y * pa.y + wa.z * pa.z + wa.w * pa.w
                  + wb.x * pb.x + wb.y * pb.y + wb.z * pb.z + wb.w * pb.w;
        #pragma unroll
        for (int off = 16; off; off >>= 1)
            acc += __shfl_down_sync(0xffffffffu, acc, off);
        if (lane == 0)
            xout[t * DIMS + o] = acc + b_enc[o];
    }
}

// ---------------- generic tiled fp32 GEMM with fused epilogues ----------------
// C[m,n] = epilogue( sum_k A[m,k] * B[k,n] ), lda=K, ldb=N (row-major), dims
// are multiples of the tile sizes (guaranteed by this problem's shapes).
enum GemmMode {
    MODE_PLAIN = 0,   // C[m*N+n] = v
    MODE_Q     = 1,   // write to [b,h,s,d]
    MODE_KT    = 2,   // write to [b,h,d,s]
    MODE_V     = 3,   // write to [b,h,s,d]
    MODE_SCORES= 4,   // batched (z), plain store, skip fully-masked causal tiles
    MODE_PV    = 5,   // batched (z), write head-concat [b,s, h*DH+n]
    MODE_SILU  = 6,   // C = v * sigmoid(v)
    MODE_RESADD= 7    // C = R + v
};

#define BM 64
#define BN 64
#define BK 16

template<int MODE>
__global__ __launch_bounds__(128)
void gemm_kernel(const float* __restrict__ A, const float* __restrict__ B,
                 float* __restrict__ C, const float* __restrict__ R,
                 int M, int N, int K,
                 long long sA, long long sB, long long sC)
{
    const int z = blockIdx.z;
    A += (size_t)z * sA;
    B += (size_t)z * sB;
    if (MODE == MODE_SCORES) C += (size_t)z * sC;

    const int m0 = blockIdx.y * BM;
    const int n0 = blockIdx.x * BN;
    if (MODE == MODE_SCORES && n0 > m0 + BM - 1) return;   // fully causal-masked tile

    __shared__ float As[BK][BM];   // [k][m]
    __shared__ float Bs[BK][BN];   // [k][n]

    const int tid  = threadIdx.x;        // 128 threads
    const int tx   = tid & 15;           // n microtile: 16 * 4 = 64
    const int ty   = tid >> 4;           // m microtile:  8 * 8 = 64
    const int arow = tid >> 1;           // A tile load: 64 rows x 16 cols
    const int acol = (tid & 1) * 8;
    const int brow = tid >> 3;           // B tile load: 16 rows x 64 cols
    const int bcol = (tid & 7) * 8;

    float acc[8][4];
    #pragma unroll
    for (int i = 0; i < 8; i++)
        #pragma unroll
        for (int j = 0; j < 4; j++) acc[i][j] = 0.f;

    for (int k0 = 0; k0 < K; k0 += BK) {
        const float4* ap = reinterpret_cast<const float4*>(
            A + (size_t)(m0 + arow) * K + k0 + acol);
        float4 a0 = ap[0], a1 = ap[1];
        As[acol + 0][arow] = a0.x; As[acol + 1][arow] = a0.y;
        As[acol + 2][arow] = a0.z; As[acol + 3][arow] = a0.w;
        As[acol + 4][arow] = a1.x; As[acol + 5][arow] = a1.y;
        As[acol + 6][arow] = a1.z; As[acol + 7][arow] = a1.w;

        const float4* bp = reinterpret_cast<const float4*>(
            B + (size_t)(k0 + brow) * N + n0 + bcol);
        float4 b0 = bp[0], b1 = bp[1];
        *reinterpret_cast<float4*>(&Bs[brow][bcol])     = b0;
        *reinterpret_cast<float4*>(&Bs[brow][bcol + 4]) = b1;

        __syncthreads();

        #pragma unroll
        for (int kk = 0; kk < BK; kk++) {
            float4 af0 = *reinterpret_cast<const float4*>(&As[kk][ty * 8]);
            float4 af1 = *reinterpret_cast<const float4*>(&As[kk][ty * 8 + 4]);
            float4 bf  = *reinterpret_cast<const float4*>(&Bs[kk][tx * 4]);
            float av[8] = {af0.x, af0.y, af0.z, af0.w, af1.x, af1.y, af1.z, af1.w};
            float bv[4] = {bf.x, bf.y, bf.z, bf.w};
            #pragma unroll
            for (int i = 0; i < 8; i++)
                #pragma unroll
                for (int j = 0; j < 4; j++)
                    acc[i][j] += av[i] * bv[j];
        }
        __syncthreads();
    }

    #pragma unroll
    for (int i = 0; i < 8; i++) {
        const int m = m0 + ty * 8 + i;
        #pragma unroll
        for (int j = 0; j < 4; j++) {
            const int n = n0 + tx * 4 + j;
            float v = acc[i][j];
            if (MODE == MODE_PLAIN || MODE == MODE_SCORES) {
                C[(size_t)m * N + n] = v;
            } else if (MODE == MODE_SILU) {
                C[(size_t)m * N + n] = v / (1.0f + expf(-v));
            } else if (MODE == MODE_RESADD) {
                C[(size_t)m * N + n] = R[(size_t)m * N + n] + v;
            } else if (MODE == MODE_Q || MODE == MODE_V) {
                const int b = m / SEQ, srow = m & (SEQ - 1);
                const int h = n / DH,  d    = n & (DH - 1);
                C[(((size_t)(b * HEADS + h) * SEQ) + srow) * DH + d] = v;
            } else if (MODE == MODE_KT) {
                const int b = m / SEQ, srow = m & (SEQ - 1);
                const int h = n / DH,  d    = n & (DH - 1);
                C[(((size_t)(b * HEADS + h) * DH) + d) * SEQ + srow] = v;
            } else if (MODE == MODE_PV) {
                const int b = z / HEADS, h = z % HEADS;
                C[((size_t)(b * SEQ) + m) * DIMS + h * DH + n] = v;
            }
        }
    }
}

// ---------------- causal softmax over rows of g_s (scale fused) ----------------
__global__ __launch_bounds__(256) void softmax_kernel(float* __restrict__ P)
{
    const int row = blockIdx.x;              // b*H*SEQ rows
    const int qi  = row & (SEQ - 1);
    float* p = P + (size_t)row * SEQ;
    const int tid = threadIdx.x;
    const float scale = 0.08838834764831845f;  // 1/sqrt(128)
    __shared__ float red[256];

    float mx = -3.4e38f;
    for (int j = tid; j <= qi; j += 256) mx = fmaxf(mx, p[j]);
    red[tid] = mx; __syncthreads();
    #pragma unroll
    for (int o = 128; o; o >>= 1) {
        if (tid < o) red[tid] = fmaxf(red[tid], red[tid + o]);
        __syncthreads();
    }
    mx = red[0] * scale;
    __syncthreads();

    float sum = 0.f;
    for (int j = tid; j <= qi; j += 256) {
        float e = expf(p[j] * scale - mx);
        p[j] = e;
        sum += e;
    }
    red[tid] = sum; __syncthreads();
    #pragma unroll
    for (int o = 128; o; o >>= 1) {
        if (tid < o) red[tid] += red[tid + o];
        __syncthreads();
    }
    const float inv = 1.f / red[0];

    for (int j = tid; j < SEQ; j += 256)
        p[j] = (j <= qi) ? p[j] * inv : 0.f;
}

// ---------------- driver ----------------
extern "C" void kernel_launch(void* const* d_in, const int* in_sizes, int n_in,
                              void* d_out, int out_size)
{
    const int*   X     = (const int*)  d_in[0];
    const float* W_enc = (const float*)d_in[1];
    const float* b_enc = (const float*)d_in[2];
    const float* Wq    = (const float*)d_in[3];
    const float* Wk    = (const float*)d_in[4];
    const float* Wv    = (const float*)d_in[5];
    const float* Wo    = (const float*)d_in[6];
    const float* W1    = (const float*)d_in[7];
    const float* W2    = (const float*)d_in[8];
    const float* W_dec = (const float*)d_in[9];
    float* out = (float*)d_out;

    float *x, *q, *kt, *v, *s, *attn, *a, *h;
    cudaGetSymbolAddress((void**)&x,    g_x);
    cudaGetSymbolAddress((void**)&q,    g_q);
    cudaGetSymbolAddress((void**)&kt,   g_kt);
    cudaGetSymbolAddress((void**)&v,    g_v);
    cudaGetSymbolAddress((void**)&s,    g_s);
    cudaGetSymbolAddress((void**)&attn, g_attn);
    cudaGetSymbolAddress((void**)&a,    g_a);
    cudaGetSymbolAddress((void**)&h,    g_h);

    encode_kernel<<<TOKENS, 256>>>(X, W_enc, b_enc, x);

    const dim3 gSq(DIMS / BN, TOKENS / BM, 1);            // [2048,256]x[256,256]
    const dim3 gSc(SEQ / BN, SEQ / BM, NB * HEADS);       // scores
    const dim3 gPV(DH / BN, SEQ / BM, NB * HEADS);        // PV
    const dim3 gM1(2 * DIMS / BN, TOKENS / BM, 1);        // MLP up
    const dim3 gDec(VOCAB / BN, TOKENS / BM, 1);          // decode

    for (int l = 0; l < NLAYERS; l++) {
        const float* wq = Wq + (size_t)l * DIMS * DIMS;
        const float* wk = Wk + (size_t)l * DIMS * DIMS;
        const float* wv = Wv + (size_t)l * DIMS * DIMS;
        const float* wo = Wo + (size_t)l * DIMS * DIMS;
        const float* w1 = W1 + (size_t)l * DIMS * 2 * DIMS;
        const float* w2 = W2 + (size_t)l * 2 * DIMS * DIMS;

        gemm_kernel<MODE_Q> <<<gSq, 128>>>(x, wq, q,  nullptr, TOKENS, DIMS, DIMS, 0, 0, 0);
        gemm_kernel<MODE_KT><<<gSq, 128>>>(x, wk, kt, nullptr, TOKENS, DIMS, DIMS, 0, 0, 0);
        gemm_kernel<MODE_V> <<<gSq, 128>>>(x, wv, v,  nullptr, TOKENS, DIMS, DIMS, 0, 0, 0);

        gemm_kernel<MODE_SCORES><<<gSc, 128>>>(q, kt, s, nullptr, SEQ, SEQ, DH,
                                               (long long)SEQ * DH,
                                               (long long)DH * SEQ,
                                               (long long)SEQ * SEQ);
        softmax_kernel<<<NB * HEADS * SEQ, 256>>>(s);
        gemm_kernel<MODE_PV><<<gPV, 128>>>(s, v, attn, nullptr, SEQ, DH, SEQ,
                                           (long long)SEQ * SEQ,
                                           (long long)SEQ * DH, 0);

        gemm_kernel<MODE_PLAIN><<<gSq, 128>>>(attn, wo, a, nullptr, TOKENS, DIMS, DIMS, 0, 0, 0);
        gemm_kernel<MODE_SILU> <<<gM1, 128>>>(a, w1, h, nullptr, TOKENS, 2 * DIMS, DIMS, 0, 0, 0);
        gemm_kernel<MODE_RESADD><<<gSq, 128>>>(h, w2, x, x, TOKENS, DIMS, 2 * DIMS, 0, 0, 0);
    }

    gemm_kernel<MODE_PLAIN><<<gDec, 128>>>(x, W_dec, out, nullptr, TOKENS, VOCAB, DIMS, 0, 0, 0);
}

// round 2
// speedup vs baseline: 1.4802x; 1.4802x over previous
#include <cuda_runtime.h>
#include <math.h>

#define DIMS    256
#define VOCAB   4096
#define HEADS   2
#define NB      2
#define SEQ     1024
#define DH      128            // DIMS / HEADS
#define TOKENS  (NB * SEQ)     // 2048
#define NLAYERS 6

// ---------------- scratch (static device memory; no allocs) ----------------
__device__ float g_x[TOKENS * DIMS];                    // activations [b,s,d]
__device__ float g_q[NB * HEADS * SEQ * DH];            // [b,h,s,d]
__device__ float g_kt[NB * HEADS * DH * SEQ];           // [b,h,d,s]  (K transposed)
__device__ float g_v[NB * HEADS * SEQ * DH];            // [b,h,s,d]
__device__ float g_s[(size_t)NB * HEADS * SEQ * SEQ];   // scores/probs [b,h,q,k]
__device__ float g_attn[TOKENS * DIMS];                 // head-concat attention out
__device__ float g_a[TOKENS * DIMS];                    // after Wo
__device__ float g_h[TOKENS * 2 * DIMS];                // MLP hidden

// ---------------- encoder ----------------
__global__ __launch_bounds__(256) void encode_kernel(
    const int* __restrict__ X, const float* __restrict__ W_enc,
    const float* __restrict__ b_enc, float* __restrict__ xout)
{
    const int t = blockIdx.x;            // token 0..2047
    const int s = t & (SEQ - 1);
    const int tid = threadIdx.x;

    __shared__ float pos[DIMS];
    {
        const int i = tid;
        const float p = (float)NB - (float)s;    // positions = B - arange(S)
        const int fi = (i < DH) ? i : i - DH;    // half = 128
        const float invf = 1.0f / powf(10000.0f, (float)fi * (1.0f / 128.0f));
        const float ang = p * invf;
        pos[i] = (i < DH) ? sinf(ang) : cosf(ang);
    }
    __syncthreads();

    const int tok = X[t];
    const int warp = tid >> 5, lane = tid & 31;

    #pragma unroll
    for (int o = warp; o < DIMS; o += 8) {
        const float* wrow = W_enc + ((size_t)o * VOCAB + tok) * DIMS;
        const float4* w4 = reinterpret_cast<const float4*>(wrow);
        const float4* p4 = reinterpret_cast<const float4*>(pos);
        float4 wa = w4[lane * 2 + 0], wb = w4[lane * 2 + 1];
        float4 pa = p4[lane * 2 + 0], pb = p4[lane * 2 + 1];
        float acc = wa.x * pa.x + wa.y * pa.y + wa.z * pa.z + wa.w * pa.w
                  + wb.x * pb.x + wb.y * pb.y + wb.z * pb.z + wb.w * pb.w;
        #pragma unroll
        for (int off = 16; off; off >>= 1)
            acc += __shfl_down_sync(0xffffffffu, acc, off);
        if (lane == 0)
            xout[t * DIMS + o] = acc + b_enc[o];
    }
}

// ---------------- tiled fp32 GEMM v2: 256 thr, 4x4 microtile, double-buffered ----
enum GemmMode {
    MODE_PLAIN = 0,
    MODE_QKV   = 1,   // z selects (Wq->Q layout, Wk->KT layout, Wv->V layout)
    MODE_SCORES= 4,   // batched, causal tile skip
    MODE_PV    = 5,   // batched, head-concat output
    MODE_SILU  = 6,
    MODE_RESADD= 7
};

#define BM 64
#define BN 64
#define BK 16

template<int MODE>
__global__ __launch_bounds__(256)
void gemm2(const float* __restrict__ A,
           const float* __restrict__ B0, const float* __restrict__ B1, const float* __restrict__ B2,
           float* __restrict__ C0, float* __restrict__ C1, float* __restrict__ C2,
           const float* __restrict__ R,
           int M, int N, int K,
           long long sA, long long sB, long long sC)
{
    const int z = blockIdx.z;
    const float* B = B0;
    float* C = C0;
    if (MODE == MODE_QKV) {
        B = (z == 0) ? B0 : (z == 1) ? B1 : B2;
        C = (z == 0) ? C0 : (z == 1) ? C1 : C2;
    } else {
        A += (size_t)z * sA;
        B += (size_t)z * sB;
        if (MODE == MODE_SCORES) C += (size_t)z * sC;
    }

    const int m0 = blockIdx.y * BM;
    const int n0 = blockIdx.x * BN;
    if (MODE == MODE_SCORES && n0 > m0 + BM - 1) return;   // fully masked causal tile

    __shared__ float As[2][BK][BM];
    __shared__ float Bs[2][BK][BN];

    const int tid = threadIdx.x;              // 256
    const int aRow = tid >> 2;                // 0..63
    const int aCol = (tid & 3) * 4;           // 0,4,8,12
    const int bRow = tid >> 4;                // 0..15
    const int bCol = (tid & 15) * 4;          // 0..60

    const float* Aptr = A + (size_t)(m0 + aRow) * K + aCol;
    const float* Bptr = B + (size_t)bRow * N + n0 + bCol;

    float4 ra = *reinterpret_cast<const float4*>(Aptr);
    float4 rb = *reinterpret_cast<const float4*>(Bptr);
    As[0][aCol + 0][aRow] = ra.x; As[0][aCol + 1][aRow] = ra.y;
    As[0][aCol + 2][aRow] = ra.z; As[0][aCol + 3][aRow] = ra.w;
    *reinterpret_cast<float4*>(&Bs[0][bRow][bCol]) = rb;
    __syncthreads();

    const int ty = tid >> 4;   // 0..15 -> rows ty*4
    const int tx = tid & 15;   // 0..15 -> cols tx*4

    float acc[4][4];
    #pragma unroll
    for (int i = 0; i < 4; i++)
        #pragma unroll
        for (int j = 0; j < 4; j++) acc[i][j] = 0.f;

    const int nk = K / BK;
    for (int kt = 0; kt < nk; kt++) {
        const int cur = kt & 1, nxt = cur ^ 1;
        if (kt + 1 < nk) {
            ra = *reinterpret_cast<const float4*>(Aptr + (kt + 1) * BK);
            rb = *reinterpret_cast<const float4*>(Bptr + (size_t)(kt + 1) * BK * N);
        }
        #pragma unroll
        for (int kk = 0; kk < BK; kk++) {
            float4 av = *reinterpret_cast<const float4*>(&As[cur][kk][ty * 4]);
            float4 bv = *reinterpret_cast<const float4*>(&Bs[cur][kk][tx * 4]);
            float a0[4] = {av.x, av.y, av.z, av.w};
            float b0[4] = {bv.x, bv.y, bv.z, bv.w};
            #pragma unroll
            for (int i = 0; i < 4; i++)
                #pragma unroll
                for (int j = 0; j < 4; j++)
                    acc[i][j] += a0[i] * b0[j];
        }
        if (kt + 1 < nk) {
            As[nxt][aCol + 0][aRow] = ra.x; As[nxt][aCol + 1][aRow] = ra.y;
            As[nxt][aCol + 2][aRow] = ra.z; As[nxt][aCol + 3][aRow] = ra.w;
            *reinterpret_cast<float4*>(&Bs[nxt][bRow][bCol]) = rb;
        }
        __syncthreads();
    }

    #pragma unroll
    for (int i = 0; i < 4; i++) {
        const int m = m0 + ty * 4 + i;
        const int n = n0 + tx * 4;
        float4 v4 = make_float4(acc[i][0], acc[i][1], acc[i][2], acc[i][3]);
        if (MODE == MODE_PLAIN || MODE == MODE_SCORES) {
            *reinterpret_cast<float4*>(&C[(size_t)m * N + n]) = v4;
        } else if (MODE == MODE_SILU) {
            v4.x = v4.x / (1.f + expf(-v4.x));
            v4.y = v4.y / (1.f + expf(-v4.y));
            v4.z = v4.z / (1.f + expf(-v4.z));
            v4.w = v4.w / (1.f + expf(-v4.w));
            *reinterpret_cast<float4*>(&C[(size_t)m * N + n]) = v4;
        } else if (MODE == MODE_RESADD) {
            float4 r4 = *reinterpret_cast<const float4*>(&R[(size_t)m * N + n]);
            v4.x += r4.x; v4.y += r4.y; v4.z += r4.z; v4.w += r4.w;
            *reinterpret_cast<float4*>(&C[(size_t)m * N + n]) = v4;
        } else if (MODE == MODE_QKV) {
            const int b = m / SEQ, srow = m & (SEQ - 1);
            const int h = n / DH,  d    = n & (DH - 1);
            if (z == 1) {  // KT: [b,h,d,s] scatter
                C[(((size_t)(b * HEADS + h) * DH) + d + 0) * SEQ + srow] = v4.x;
                C[(((size_t)(b * HEADS + h) * DH) + d + 1) * SEQ + srow] = v4.y;
                C[(((size_t)(b * HEADS + h) * DH) + d + 2) * SEQ + srow] = v4.z;
                C[(((size_t)(b * HEADS + h) * DH) + d + 3) * SEQ + srow] = v4.w;
            } else {       // Q or V: [b,h,s,d]
                *reinterpret_cast<float4*>(
                    &C[(((size_t)(b * HEADS + h) * SEQ) + srow) * DH + d]) = v4;
            }
        } else if (MODE == MODE_PV) {
            const int b = z / HEADS, h = z % HEADS;
            *reinterpret_cast<float4*>(
                &C[((size_t)(b * SEQ) + m) * DIMS + h * DH + n]) = v4;
        }
    }
}

// ---------------- causal softmax (scale fused) ----------------
__global__ __launch_bounds__(256) void softmax_kernel(float* __restrict__ P)
{
    const int row = blockIdx.x;
    const int qi  = row & (SEQ - 1);
    float* p = P + (size_t)row * SEQ;
    const int tid = threadIdx.x;
    const float scale = 0.08838834764831845f;  // 1/sqrt(128)
    __shared__ float red[256];

    float mx = -3.4e38f;
    for (int j = tid; j <= qi; j += 256) mx = fmaxf(mx, p[j]);
    red[tid] = mx; __syncthreads();
    #pragma unroll
    for (int o = 128; o; o >>= 1) {
        if (tid < o) red[tid] = fmaxf(red[tid], red[tid + o]);
        __syncthreads();
    }
    mx = red[0] * scale;
    __syncthreads();

    float sum = 0.f;
    for (int j = tid; j <= qi; j += 256) {
        float e = expf(p[j] * scale - mx);
        p[j] = e;
        sum += e;
    }
    red[tid] = sum; __syncthreads();
    #pragma unroll
    for (int o = 128; o; o >>= 1) {
        if (tid < o) red[tid] += red[tid + o];
        __syncthreads();
    }
    const float inv = 1.f / red[0];

    for (int j = tid; j < SEQ; j += 256)
        p[j] = (j <= qi) ? p[j] * inv : 0.f;
}

// ---------------- driver ----------------
extern "C" void kernel_launch(void* const* d_in, const int* in_sizes, int n_in,
                              void* d_out, int out_size)
{
    const int*   X     = (const int*)  d_in[0];
    const float* W_enc = (const float*)d_in[1];
    const float* b_enc = (const float*)d_in[2];
    const float* Wq    = (const float*)d_in[3];
    const float* Wk    = (const float*)d_in[4];
    const float* Wv    = (const float*)d_in[5];
    const float* Wo    = (const float*)d_in[6];
    const float* W1    = (const float*)d_in[7];
    const float* W2    = (const float*)d_in[8];
    const float* W_dec = (const float*)d_in[9];
    float* out = (float*)d_out;

    float *x, *q, *kt, *v, *s, *attn, *a, *h;
    cudaGetSymbolAddress((void**)&x,    g_x);
    cudaGetSymbolAddress((void**)&q,    g_q);
    cudaGetSymbolAddress((void**)&kt,   g_kt);
    cudaGetSymbolAddress((void**)&v,    g_v);
    cudaGetSymbolAddress((void**)&s,    g_s);
    cudaGetSymbolAddress((void**)&attn, g_attn);
    cudaGetSymbolAddress((void**)&a,    g_a);
    cudaGetSymbolAddress((void**)&h,    g_h);

    encode_kernel<<<TOKENS, 256>>>(X, W_enc, b_enc, x);

    const dim3 gQKV(DIMS / BN, TOKENS / BM, 3);
    const dim3 gSq (DIMS / BN, TOKENS / BM, 1);
    const dim3 gSc (SEQ / BN, SEQ / BM, NB * HEADS);
    const dim3 gPV (DH / BN, SEQ / BM, NB * HEADS);
    const dim3 gM1 (2 * DIMS / BN, TOKENS / BM, 1);
    const dim3 gDec(VOCAB / BN, TOKENS / BM, 1);

    for (int l = 0; l < NLAYERS; l++) {
        const float* wq = Wq + (size_t)l * DIMS * DIMS;
        const float* wk = Wk + (size_t)l * DIMS * DIMS;
        const float* wv = Wv + (size_t)l * DIMS * DIMS;
        const float* wo = Wo + (size_t)l * DIMS * DIMS;
        const float* w1 = W1 + (size_t)l * DIMS * 2 * DIMS;
        const float* w2 = W2 + (size_t)l * 2 * DIMS * DIMS;

        gemm2<MODE_QKV><<<gQKV, 256>>>(x, wq, wk, wv, q, kt, v, nullptr,
                                       TOKENS, DIMS, DIMS, 0, 0, 0);

        gemm2<MODE_SCORES><<<gSc, 256>>>(q, kt, nullptr, nullptr, s, nullptr, nullptr, nullptr,
                                         SEQ, SEQ, DH,
                                         (long long)SEQ * DH,
                                         (long long)DH * SEQ,
                                         (long long)SEQ * SEQ);
        softmax_kernel<<<NB * HEADS * SEQ, 256>>>(s);
        gemm2<MODE_PV><<<gPV, 256>>>(s, v, nullptr, nullptr, attn, nullptr, nullptr, nullptr,
                                     SEQ, DH, SEQ,
                                     (long long)SEQ * SEQ,
                                     (long long)SEQ * DH, 0);

        gemm2<MODE_PLAIN><<<gSq, 256>>>(attn, wo, nullptr, nullptr, a, nullptr, nullptr, nullptr,
                                        TOKENS, DIMS, DIMS, 0, 0, 0);
        gemm2<MODE_SILU><<<gM1, 256>>>(a, w1, nullptr, nullptr, h, nullptr, nullptr, nullptr,
                                       TOKENS, 2 * DIMS, DIMS, 0, 0, 0);
        gemm2<MODE_RESADD><<<gSq, 256>>>(h, w2, nullptr, nullptr, x, nullptr, nullptr, x,
                                         TOKENS, DIMS, 2 * DIMS, 0, 0, 0);
    }

    gemm2<MODE_PLAIN><<<gDec, 256>>>(x, W_dec, nullptr, nullptr, out, nullptr, nullptr, nullptr,
                                     TOKENS, VOCAB, DIMS, 0, 0, 0);
}

// round 6
// speedup vs baseline: 1.8020x; 1.2174x over previous
#include <cuda_runtime.h>
#include <math.h>
#include <stdint.h>

#define DIMS    256
#define VOCAB   4096
#define HEADS   2
#define NB      2
#define SEQ     1024
#define DH      128
#define TOKENS  (NB * SEQ)
#define NLAYERS 6

// ---------------- scratch ----------------
__device__ float g_x[TOKENS * DIMS];
__device__ float g_q[NB * HEADS * SEQ * DH];
__device__ float g_kt[NB * HEADS * DH * SEQ];
__device__ float g_v[NB * HEADS * SEQ * DH];
__device__ float g_s[(size_t)NB * HEADS * SEQ * SEQ];
__device__ float g_attn[TOKENS * DIMS];
__device__ float g_a[TOKENS * DIMS];
__device__ float g_h[TOKENS * 2 * DIMS];

// ---------------- encoder ----------------
__global__ __launch_bounds__(256) void encode_kernel(
    const int* __restrict__ X, const float* __restrict__ W_enc,
    const float* __restrict__ b_enc, float* __restrict__ xout)
{
    const int t = blockIdx.x;
    const int s = t & (SEQ - 1);
    const int tid = threadIdx.x;

    __shared__ float pos[DIMS];
    {
        const int i = tid;
        const float p = (float)NB - (float)s;
        const int fi = (i < DH) ? i : i - DH;
        const float invf = 1.0f / powf(10000.0f, (float)fi * (1.0f / 128.0f));
        const float ang = p * invf;
        pos[i] = (i < DH) ? sinf(ang) : cosf(ang);
    }
    __syncthreads();

    const int tok = X[t];
    const int warp = tid >> 5, lane = tid & 31;

    #pragma unroll
    for (int o = warp; o < DIMS; o += 8) {
        const float* wrow = W_enc + ((size_t)o * VOCAB + tok) * DIMS;
        const float4* w4 = reinterpret_cast<const float4*>(wrow);
        const float4* p4 = reinterpret_cast<const float4*>(pos);
        float4 wa = w4[lane * 2 + 0], wb = w4[lane * 2 + 1];
        float4 pa = p4[lane * 2 + 0], pb = p4[lane * 2 + 1];
        float acc = wa.x * pa.x + wa.y * pa.y + wa.z * pa.z + wa.w * pa.w
                  + wb.x * pb.x + wb.y * pb.y + wb.z * pb.z + wb.w * pb.w;
        #pragma unroll
        for (int off = 16; off; off >>= 1)
            acc += __shfl_down_sync(0xffffffffu, acc, off);
        if (lane == 0)
            xout[t * DIMS + o] = acc + b_enc[o];
    }
}

// ---------------- tf32 tensor-core GEMM ----------------
enum GemmMode {
    MODE_PLAIN = 0,
    MODE_QKV   = 1,
    MODE_SCORES= 4,
    MODE_PV    = 5,
    MODE_SILU  = 6,
    MODE_RESADD= 7
};

#define BM 64
#define BN 64
#define BK 16
#define PADK 20          // padded row stride (floats): 80B -> conflict-free ldmatrix

__device__ __forceinline__ uint32_t f2tf32(float f) {
    uint32_t r;
    asm("cvt.rna.tf32.f32 %0, %1;" : "=r"(r) : "f"(f));
    return r;
}

__device__ __forceinline__ void ldm_x4(uint32_t& r0, uint32_t& r1, uint32_t& r2, uint32_t& r3,
                                       uint32_t addr) {
    asm volatile("ldmatrix.sync.aligned.m8n8.x4.shared.b16 {%0,%1,%2,%3}, [%4];"
                 : "=r"(r0), "=r"(r1), "=r"(r2), "=r"(r3) : "r"(addr));
}

__device__ __forceinline__ void mma_tf32(float* c, const uint32_t* a, const uint32_t* b) {
    asm volatile("mma.sync.aligned.m16n8k8.row.col.f32.tf32.tf32.f32 "
                 "{%0,%1,%2,%3}, {%4,%5,%6,%7}, {%8,%9}, {%0,%1,%2,%3};"
                 : "+f"(c[0]), "+f"(c[1]), "+f"(c[2]), "+f"(c[3])
                 : "r"(a[0]), "r"(a[1]), "r"(a[2]), "r"(a[3]), "r"(b[0]), "r"(b[1]));
}

template<int MODE>
__global__ __launch_bounds__(128)
void gemm3(const float* __restrict__ A,
           const float* __restrict__ B0, const float* __restrict__ B1, const float* __restrict__ B2,
           float* __restrict__ C0, float* __restrict__ C1, float* __restrict__ C2,
           const float* __restrict__ R,
           int M, int N, int K,
           long long sA, long long sB, long long sC)
{
    const int z = blockIdx.z;
    const float* B = B0;
    float* C = C0;
    if (MODE == MODE_QKV) {
        B = (z == 0) ? B0 : (z == 1) ? B1 : B2;
        C = (z == 0) ? C0 : (z == 1) ? C1 : C2;
    } else {
        A += (size_t)z * sA;
        B += (size_t)z * sB;
        if (MODE == MODE_SCORES) C += (size_t)z * sC;
    }

    const int m0 = blockIdx.y * BM;
    const int n0 = blockIdx.x * BN;
    if (MODE == MODE_SCORES && n0 > m0 + BM - 1) return;

    __shared__ uint32_t As[2][BM * PADK];
    __shared__ uint32_t Bs[2][BN * PADK];

    const int tid  = threadIdx.x;
    const int lane = tid & 31;
    const int wid  = tid >> 5;          // 4 warps
    const int wm   = wid >> 1;          // 0..1 -> m offset wm*32
    const int wn   = wid & 1;           // 0..1 -> n offset wn*32

    // A loader: row = tid>>1 (0..63), half = (tid&1)*8
    const int aRow = tid >> 1;
    const int aColH = (tid & 1) * 8;
    const float* gA = A + (size_t)(m0 + aRow) * K + aColH;

    // B loader: n = tid&63, quads {2*(tid>>6), 2*(tid>>6)+1}
    const int bN = tid & 63;
    const int bQ = (tid >> 6) * 2;
    const float* gB = B + n0 + bN;

    // ldmatrix per-lane offsets
    const int grp = lane >> 3, lr = lane & 7;
    const int aRowOff = (grp & 1) * 8 + lr;
    const int aKoff   = (grp >> 1) * 4;
    const int bRowOff = (grp >> 1) * 8 + lr;
    const int bKoff   = (grp & 1) * 4;

    float acc[2][4][4];
    #pragma unroll
    for (int i = 0; i < 2; i++)
        #pragma unroll
        for (int j = 0; j < 4; j++)
            #pragma unroll
            for (int r = 0; r < 4; r++) acc[i][j][r] = 0.f;

    const int nk = K / BK;

    // prologue: stage 0
    {
        float4 ra0 = *reinterpret_cast<const float4*>(gA);
        float4 ra1 = *reinterpret_cast<const float4*>(gA + 4);
        uint4 ua0 = make_uint4(f2tf32(ra0.x), f2tf32(ra0.y), f2tf32(ra0.z), f2tf32(ra0.w));
        uint4 ua1 = make_uint4(f2tf32(ra1.x), f2tf32(ra1.y), f2tf32(ra1.z), f2tf32(ra1.w));
        *reinterpret_cast<uint4*>(&As[0][aRow * PADK + aColH])     = ua0;
        *reinterpret_cast<uint4*>(&As[0][aRow * PADK + aColH + 4]) = ua1;

        #pragma unroll
        for (int q2 = 0; q2 < 2; q2++) {
            const int q = bQ + q2;
            float r0 = gB[(size_t)(q * 4 + 0) * N];
            float r1 = gB[(size_t)(q * 4 + 1) * N];
            float r2 = gB[(size_t)(q * 4 + 2) * N];
            float r3 = gB[(size_t)(q * 4 + 3) * N];
            uint4 ub = make_uint4(f2tf32(r0), f2tf32(r1), f2tf32(r2), f2tf32(r3));
            *reinterpret_cast<uint4*>(&Bs[0][bN * PADK + q * 4]) = ub;
        }
    }
    __syncthreads();

    for (int kt = 0; kt < nk; kt++) {
        const int cur = kt & 1, nxt = cur ^ 1;
        float4 ra0, ra1;
        float rb[8];
        const bool more = (kt + 1 < nk);
        if (more) {
            const float* pA = gA + (kt + 1) * BK;
            ra0 = *reinterpret_cast<const float4*>(pA);
            ra1 = *reinterpret_cast<const float4*>(pA + 4);
            const float* pB = gB + (size_t)(kt + 1) * BK * N;
            #pragma unroll
            for (int q2 = 0; q2 < 2; q2++)
                #pragma unroll
                for (int j = 0; j < 4; j++)
                    rb[q2 * 4 + j] = pB[(size_t)((bQ + q2) * 4 + j) * N];
        }

        const uint32_t aBase = (uint32_t)__cvta_generic_to_shared(&As[cur][0]);
        const uint32_t bBase = (uint32_t)__cvta_generic_to_shared(&Bs[cur][0]);

        #pragma unroll
        for (int kc = 0; kc < 2; kc++) {
            uint32_t af[2][4], bf[4][2];
            #pragma unroll
            for (int mt = 0; mt < 2; mt++) {
                uint32_t addr = aBase + 4u * ((wm * 32 + mt * 16 + aRowOff) * PADK + kc * 8 + aKoff);
                ldm_x4(af[mt][0], af[mt][1], af[mt][2], af[mt][3], addr);
            }
            #pragma unroll
            for (int nt2 = 0; nt2 < 2; nt2++) {
                uint32_t r0, r1, r2, r3;
                uint32_t addr = bBase + 4u * ((wn * 32 + nt2 * 16 + bRowOff) * PADK + kc * 8 + bKoff);
                ldm_x4(r0, r1, r2, r3, addr);
                bf[nt2 * 2 + 0][0] = r0; bf[nt2 * 2 + 0][1] = r1;
                bf[nt2 * 2 + 1][0] = r2; bf[nt2 * 2 + 1][1] = r3;
            }
            #pragma unroll
            for (int mt = 0; mt < 2; mt++)
                #pragma unroll
                for (int nt = 0; nt < 4; nt++)
                    mma_tf32(acc[mt][nt], af[mt], bf[nt]);
        }

        if (more) {
            uint4 ua0 = make_uint4(f2tf32(ra0.x), f2tf32(ra0.y), f2tf32(ra0.z), f2tf32(ra0.w));
            uint4 ua1 = make_uint4(f2tf32(ra1.x), f2tf32(ra1.y), f2tf32(ra1.z), f2tf32(ra1.w));
            *reinterpret_cast<uint4*>(&As[nxt][aRow * PADK + aColH])     = ua0;
            *reinterpret_cast<uint4*>(&As[nxt][aRow * PADK + aColH + 4]) = ua1;
            #pragma unroll
            for (int q2 = 0; q2 < 2; q2++) {
                uint4 ub = make_uint4(f2tf32(rb[q2 * 4 + 0]), f2tf32(rb[q2 * 4 + 1]),
                                      f2tf32(rb[q2 * 4 + 2]), f2tf32(rb[q2 * 4 + 3]));
                *reinterpret_cast<uint4*>(&Bs[nxt][bN * PADK + (bQ + q2) * 4]) = ub;
            }
        }
        __syncthreads();
    }

    // ---------------- epilogue ----------------
    #pragma unroll
    for (int mt = 0; mt < 2; mt++) {
        #pragma unroll
        for (int nt = 0; nt < 4; nt++) {
            const int mrow = m0 + wm * 32 + mt * 16 + (lane >> 2);
            const int ncol = n0 + wn * 32 + nt * 8 + 2 * (lane & 3);
            float c[4] = {acc[mt][nt][0], acc[mt][nt][1], acc[mt][nt][2], acc[mt][nt][3]};

            #pragma unroll
            for (int half = 0; half < 2; half++) {
                const int m = mrow + half * 8;
                float v0 = c[half * 2 + 0], v1 = c[half * 2 + 1];
                if (MODE == MODE_PLAIN || MODE == MODE_SCORES) {
                    *reinterpret_cast<float2*>(&C[(size_t)m * N + ncol]) = make_float2(v0, v1);
                } else if (MODE == MODE_SILU) {
                    v0 = v0 / (1.f + expf(-v0));
                    v1 = v1 / (1.f + expf(-v1));
                    *reinterpret_cast<float2*>(&C[(size_t)m * N + ncol]) = make_float2(v0, v1);
                } else if (MODE == MODE_RESADD) {
                    float2 r2 = *reinterpret_cast<const float2*>(&R[(size_t)m * N + ncol]);
                    *reinterpret_cast<float2*>(&C[(size_t)m * N + ncol]) =
                        make_float2(v0 + r2.x, v1 + r2.y);
                } else if (MODE == MODE_QKV) {
                    const int b = m / SEQ, srow = m & (SEQ - 1);
                    const int h = ncol / DH, d = ncol & (DH - 1);
                    if (z == 1) {  // KT [b,h,d,s]
                        C[(((size_t)(b * HEADS + h) * DH) + d + 0) * SEQ + srow] = v0;
                        C[(((size_t)(b * HEADS + h) * DH) + d + 1) * SEQ + srow] = v1;
                    } else {       // Q/V [b,h,s,d]
                        *reinterpret_cast<float2*>(
                            &C[(((size_t)(b * HEADS + h) * SEQ) + srow) * DH + d]) =
                            make_float2(v0, v1);
                    }
                } else if (MODE == MODE_PV) {
                    const int b = z / HEADS, h = z % HEADS;
                    *reinterpret_cast<float2*>(
                        &C[((size_t)(b * SEQ) + m) * DIMS + h * DH + ncol]) =
                        make_float2(v0, v1);
                }
            }
        }
    }
}

// ---------------- causal softmax ----------------
__global__ __launch_bounds__(256) void softmax_kernel(float* __restrict__ P)
{
    const int row = blockIdx.x;
    const int qi  = row & (SEQ - 1);
    float* p = P + (size_t)row * SEQ;
    const int tid = threadIdx.x;
    const float scale = 0.08838834764831845f;
    __shared__ float red[256];

    float mx = -3.4e38f;
    for (int j = tid; j <= qi; j += 256) mx = fmaxf(mx, p[j]);
    red[tid] = mx; __syncthreads();
    #pragma unroll
    for (int o = 128; o; o >>= 1) {
        if (tid < o) red[tid] = fmaxf(red[tid], red[tid + o]);
        __syncthreads();
    }
    mx = red[0] * scale;
    __syncthreads();

    float sum = 0.f;
    for (int j = tid; j <= qi; j += 256) {
        float e = expf(p[j] * scale - mx);
        p[j] = e;
        sum += e;
    }
    red[tid] = sum; __syncthreads();
    #pragma unroll
    for (int o = 128; o; o >>= 1) {
        if (tid < o) red[tid] += red[tid + o];
        __syncthreads();
    }
    const float inv = 1.f / red[0];

    for (int j = tid; j < SEQ; j += 256)
        p[j] = (j <= qi) ? p[j] * inv : 0.f;
}

// ---------------- driver ----------------
extern "C" void kernel_launch(void* const* d_in, const int* in_sizes, int n_in,
                              void* d_out, int out_size)
{
    const int*   X     = (const int*)  d_in[0];
    const float* W_enc = (const float*)d_in[1];
    const float* b_enc = (const float*)d_in[2];
    const float* Wq    = (const float*)d_in[3];
    const float* Wk    = (const float*)d_in[4];
    const float* Wv    = (const float*)d_in[5];
    const float* Wo    = (const float*)d_in[6];
    const float* W1    = (const float*)d_in[7];
    const float* W2    = (const float*)d_in[8];
    const float* W_dec = (const float*)d_in[9];
    float* out = (float*)d_out;

    float *x, *q, *kt, *v, *s, *attn, *a, *h;
    cudaGetSymbolAddress((void**)&x,    g_x);
    cudaGetSymbolAddress((void**)&q,    g_q);
    cudaGetSymbolAddress((void**)&kt,   g_kt);
    cudaGetSymbolAddress((void**)&v,    g_v);
    cudaGetSymbolAddress((void**)&s,    g_s);
    cudaGetSymbolAddress((void**)&attn, g_attn);
    cudaGetSymbolAddress((void**)&a,    g_a);
    cudaGetSymbolAddress((void**)&h,    g_h);

    encode_kernel<<<TOKENS, 256>>>(X, W_enc, b_enc, x);

    const dim3 gQKV(DIMS / BN, TOKENS / BM, 3);
    const dim3 gSq (DIMS / BN, TOKENS / BM, 1);
    const dim3 gSc (SEQ / BN, SEQ / BM, NB * HEADS);
    const dim3 gPV (DH / BN, SEQ / BM, NB * HEADS);
    const dim3 gM1 (2 * DIMS / BN, TOKENS / BM, 1);
    const dim3 gDec(VOCAB / BN, TOKENS / BM, 1);

    for (int l = 0; l < NLAYERS; l++) {
        const float* wq = Wq + (size_t)l * DIMS * DIMS;
        const float* wk = Wk + (size_t)l * DIMS * DIMS;
        const float* wv = Wv + (size_t)l * DIMS * DIMS;
        const float* wo = Wo + (size_t)l * DIMS * DIMS;
        const float* w1 = W1 + (size_t)l * DIMS * 2 * DIMS;
        const float* w2 = W2 + (size_t)l * 2 * DIMS * DIMS;

        gemm3<MODE_QKV><<<gQKV, 128>>>(x, wq, wk, wv, q, kt, v, nullptr,
                                       TOKENS, DIMS, DIMS, 0, 0, 0);
        gemm3<MODE_SCORES><<<gSc, 128>>>(q, kt, nullptr, nullptr, s, nullptr, nullptr, nullptr,
                                         SEQ, SEQ, DH,
                                         (long long)SEQ * DH,
                                         (long long)DH * SEQ,
                                         (long long)SEQ * SEQ);
        softmax_kernel<<<NB * HEADS * SEQ, 256>>>(s);
        gemm3<MODE_PV><<<gPV, 128>>>(s, v, nullptr, nullptr, attn, nullptr, nullptr, nullptr,
                                     SEQ, DH, SEQ,
                                     (long long)SEQ * SEQ,
                                     (long long)SEQ * DH, 0);
        gemm3<MODE_PLAIN><<<gSq, 128>>>(attn, wo, nullptr, nullptr, a, nullptr, nullptr, nullptr,
                                        TOKENS, DIMS, DIMS, 0, 0, 0);
        gemm3<MODE_SILU><<<gM1, 128>>>(a, w1, nullptr, nullptr, h, nullptr, nullptr, nullptr,
                                       TOKENS, 2 * DIMS, DIMS, 0, 0, 0);
        gemm3<MODE_RESADD><<<gSq, 128>>>(h, w2, nullptr, nullptr, x, nullptr, nullptr, x,
                                         TOKENS, DIMS, 2 * DIMS, 0, 0, 0);
    }

    gemm3<MODE_PLAIN><<<gDec, 128>>>(x, W_dec, nullptr, nullptr, out, nullptr, nullptr, nullptr,
                                     TOKENS, VOCAB, DIMS, 0, 0, 0);
}